// round 6
// baseline (speedup 1.0000x reference)
#include <cuda_runtime.h>
#include <math.h>

#define NDIM 64
#define NB 64
#define MAXT 512
#define PAD 65
#define NMAT (NDIM*PAD)
#define HL2PI 0.91893853320467274178f
#define R_SMEM (9*NMAT*4)
#define M_SMEM ((3*8192 + 4096)*4)
#define NSEG 18

// ---------------- static device scratch ----------------
__device__ float g_KT[(MAXT+1)*NDIM*NDIM];
__device__ float g_SI[(MAXT+1)*NDIM*NDIM];
__device__ float g_postP[(MAXT+1)*NDIM*NDIM];
__device__ float g_pref[MAXT+1];
__device__ float g_W4[2*NDIM*NDIM];   // packed {F^T,(HF)^T}
__device__ float g_K4[2*NDIM*NDIM];   // packed {K^T_inf, SI_inf}
__device__ float g_WU[2*NDIM*NDIM];   // packed {A^T, K^T_inf} for folded warm-up
__device__ float g_c2[NDIM];
__device__ float g_o0[NDIM];
__device__ float g_d0[NDIM];
__device__ int   g_tfreeze;
__device__ int   g_Wwarm;

// ---------------- 64x64 matmul on PAD-strided smem, 256 threads ----------------
template<bool TA, bool TB>
__device__ __forceinline__ void mm64(float* C, const float* A, const float* B,
                                     const float* Cadd, float sgn)
{
    const int tid = threadIdx.x;
    const int i0 = (tid >> 4) << 2;
    const int j0 = (tid & 15) << 2;
    float acc[4][4];
#pragma unroll
    for (int r = 0; r < 4; r++)
#pragma unroll
        for (int c = 0; c < 4; c++) acc[r][c] = 0.f;
#pragma unroll 4
    for (int k = 0; k < NDIM; k++) {
        float a[4], b[4];
#pragma unroll
        for (int r = 0; r < 4; r++) a[r] = TA ? A[k*PAD + (i0+r)] : A[(i0+r)*PAD + k];
#pragma unroll
        for (int c = 0; c < 4; c++) b[c] = TB ? B[(j0+c)*PAD + k] : B[k*PAD + (j0+c)];
#pragma unroll
        for (int r = 0; r < 4; r++)
#pragma unroll
            for (int c = 0; c < 4; c++) acc[r][c] += a[r] * b[c];
    }
#pragma unroll
    for (int r = 0; r < 4; r++)
#pragma unroll
        for (int c = 0; c < 4; c++) {
            float base = Cadd ? Cadd[(i0+r)*PAD + (j0+c)] : 0.f;
            C[(i0+r)*PAD + (j0+c)] = base + sgn * acc[r][c];
        }
}

template<bool TA, bool TB>
__device__ __forceinline__ void mm64_sym(float* C, const float* A, const float* B,
                                         const float* Cadd, float sgn,
                                         int i0, int j0, bool act)
{
    if (!act) return;
    float acc[4][4];
#pragma unroll
    for (int r = 0; r < 4; r++)
#pragma unroll
        for (int c = 0; c < 4; c++) acc[r][c] = 0.f;
#pragma unroll 4
    for (int k = 0; k < NDIM; k++) {
        float a[4], b[4];
#pragma unroll
        for (int r = 0; r < 4; r++) a[r] = TA ? A[k*PAD + (i0+r)] : A[(i0+r)*PAD + k];
#pragma unroll
        for (int c = 0; c < 4; c++) b[c] = TB ? B[(j0+c)*PAD + k] : B[k*PAD + (j0+c)];
#pragma unroll
        for (int r = 0; r < 4; r++)
#pragma unroll
            for (int c = 0; c < 4; c++) acc[r][c] += a[r] * b[c];
    }
#pragma unroll
    for (int r = 0; r < 4; r++)
#pragma unroll
        for (int c = 0; c < 4; c++) {
            float base = Cadd ? Cadd[(i0+r)*PAD + (j0+c)] : 0.f;
            float v = base + sgn * acc[r][c];
            C[(i0+r)*PAD + (j0+c)] = v;
            if (i0 != j0) C[(j0+c)*PAD + (i0+r)] = v;
        }
}

__device__ __forceinline__ void ld_mat(float* dst, const float* __restrict__ src) {
    for (int idx = threadIdx.x; idx < NDIM*NDIM; idx += blockDim.x)
        dst[(idx >> 6)*PAD + (idx & 63)] = src[idx];
}

// =======================================================================
// Phase 1: Riccati recursion, one CTA, 256 threads. Publishes per-t gains
// plus EXTRAPOLATED fixed-point matrices in slot (tf+1).
// =======================================================================
__global__ void riccati_kernel(const float* __restrict__ prior_chol,
                               const float* __restrict__ Fw,
                               const float* __restrict__ dyn_chol,
                               const float* __restrict__ Hw,
                               const float* __restrict__ obs_chol,
                               const float* __restrict__ pm0,
                               const float* __restrict__ db,
                               const float* __restrict__ ob,
                               int T)
{
    extern __shared__ float sm[];
    float* sP    = sm + 0*NMAT;
    float* sT    = sm + 1*NMAT;
    float* sCW   = sm + 2*NMAT;
    float* sSa   = sm + 3*NMAT;
    float* sF    = sm + 4*NMAT;
    float* sH    = sm + 5*NMAT;
    float* sQ    = sm + 6*NMAT;
    float* sR    = sm + 7*NMAT;
    float* sPrev = sm + 8*NMAT;
    __shared__ float s_red8[8];
    __shared__ float s_row[2][NDIM];
    __shared__ float s_col[2][NDIM];
    __shared__ float s_c2s[NDIM];
    __shared__ int   s_conv;
    __shared__ float s_ratio;

    const int tid = threadIdx.x;
    const int gi0 = (tid >> 4) << 2;
    const int gj0 = (tid & 15) << 2;

    int sbi = -1, sbj = 0;
    {
        int acc = 0;
#pragma unroll
        for (int r = 0; r < 16; r++) {
            int cnt = 16 - r;
            if (tid >= acc && tid < acc + cnt) { sbi = r; sbj = r + (tid - acc); }
            acc += cnt;
        }
    }
    const bool s_act = (sbi >= 0);
    const int si0 = sbi << 2, sj0 = sbj << 2;

    ld_mat(sF, Fw); ld_mat(sH, Hw); ld_mat(sT, dyn_chol);
    __syncthreads();
    mm64_sym<false,true>(sQ, sT, sT, nullptr, 1.f, si0, sj0, s_act);
    __syncthreads();
    ld_mat(sT, obs_chol);
    __syncthreads();
    mm64_sym<false,true>(sR, sT, sT, nullptr, 1.f, si0, sj0, s_act);
    __syncthreads();
    ld_mat(sT, prior_chol);
    __syncthreads();
    mm64_sym<false,true>(sP, sT, sT, nullptr, 1.f, si0, sj0, s_act);
    __syncthreads();

    mm64<false,false>(sT, sH, sF, nullptr, 1.f);   // HF
    __syncthreads();
    for (int idx = tid; idx < NDIM*NDIM; idx += 256) {
        int k = idx >> 6, j = idx & 63;
        int base = (((k >> 1)*64 + j) << 2) + ((k & 1) << 1);
        g_W4[base + 0] = sF[j*PAD + k];
        g_W4[base + 1] = sT[j*PAD + k];
    }
    if (tid < NDIM) {
        float c = 0.f, o0 = 0.f;
        for (int k = 0; k < NDIM; k++) {
            float h = sH[tid*PAD + k];
            c  += h * db[k];
            o0 += h * pm0[k];
        }
        s_c2s[tid] = c + ob[tid];
        g_c2[tid] = c + ob[tid];
        g_o0[tid] = o0 + ob[tid];
    }
    __syncthreads();

    int tf = T;
    float rprev = 1e30f;
    for (int t = 0; t <= T; t++) {
        if (t > 0) {
            mm64<false,false>(sT, sF, sP, nullptr, 1.f);
            __syncthreads();
            mm64_sym<false,true>(sP, sT, sF, sQ, 1.f, si0, sj0, s_act);
            __syncthreads();
        }
        mm64<false,true>(sCW, sP, sH, nullptr, 1.f);
        __syncthreads();
        mm64_sym<false,false>(sSa, sH, sCW, sR, 1.f, si0, sj0, s_act);
        __syncthreads();

        // ---- register-resident Gauss-Jordan inversion of S ----
        {
            float a[4][4];
#pragma unroll
            for (int r = 0; r < 4; r++)
#pragma unroll
                for (int c = 0; c < 4; c++) a[r][c] = sSa[(gi0+r)*PAD + gj0 + c];

            float logsum = 0.f;
            for (int p = 0; p < NDIM; p++) {
                const int buf = p & 1;
                if ((p >> 2) == (tid >> 4)) {
                    const int pr = p - gi0;
#pragma unroll
                    for (int c = 0; c < 4; c++) s_row[buf][gj0 + c] = a[pr][c];
                }
                if ((p >> 2) == (tid & 15)) {
                    const int pc = p - gj0;
#pragma unroll
                    for (int r = 0; r < 4; r++) s_col[buf][gi0 + r] = a[r][pc];
                }
                __syncthreads();
                const float piv = s_row[buf][p];
                const float d = 1.0f / piv;
                if (tid == 0) logsum += logf(piv);
                float4 rowv = *(const float4*)&s_row[buf][gj0];
                float4 colv = *(const float4*)&s_col[buf][gi0];
                const float* rv = (const float*)&rowv;
                const float* cv = (const float*)&colv;
#pragma unroll
                for (int r = 0; r < 4; r++) {
                    const float aip = cv[r];
                    const bool ip = (gi0 + r == p);
#pragma unroll
                    for (int c = 0; c < 4; c++) {
                        const float apj = rv[c];
                        const bool jp = (gj0 + c == p);
                        float v = a[r][c] - aip * apj * d;
                        if (ip) v = apj * d;
                        if (jp) v = -aip * d;
                        if (ip && jp) v = d;
                        a[r][c] = v;
                    }
                }
            }
            if (tid == 0) g_pref[t] = -NDIM * HL2PI - 0.5f * logsum;
#pragma unroll
            for (int r = 0; r < 4; r++)
#pragma unroll
                for (int c = 0; c < 4; c++) sSa[(gi0+r)*PAD + gj0 + c] = a[r][c];
        }
        __syncthreads();

        mm64<true,true>(sT, sSa, sCW, nullptr, 1.f);
        __syncthreads();
        mm64_sym<true,true>(sP, sT, sCW, sP, -1.f, si0, sj0, s_act);
        __syncthreads();

        float mymax = 0.f;
        const size_t off = (size_t)t * NDIM * NDIM;
        for (int idx = tid; idx < NDIM*NDIM; idx += 256) {
            int i = idx >> 6, j = idx & 63;
            float v = sP[i*PAD + j];
            mymax = fmaxf(mymax, fabsf(v - sPrev[i*PAD + j]));
            sPrev[i*PAD + j] = v;
            g_postP[off + idx] = v;
            g_KT[off + idx]    = sT[i*PAD + j];
            g_SI[off + idx]    = sSa[i*PAD + j];
        }
#pragma unroll
        for (int o = 16; o > 0; o >>= 1)
            mymax = fmaxf(mymax, __shfl_xor_sync(0xffffffffu, mymax, o));
        if ((tid & 31) == 0) s_red8[tid >> 5] = mymax;
        __syncthreads();
        if (tid == 0) {
            float mx = s_red8[0];
#pragma unroll
            for (int i = 1; i < 8; i++) mx = fmaxf(mx, s_red8[i]);
            s_ratio = mx / fmaxf(rprev, 1e-30f);
            rprev = mx;
            s_conv = (t >= 1 && mx < 3e-5f) ? 1 : 0;
        }
        __syncthreads();
        if (s_conv) { tf = t; break; }
    }

    // ---- epilogue: Aitken extrapolation to the fixed point (slot fz=tf+1) ----
    const int fz = (tf + 1 <= MAXT) ? tf + 1 : MAXT;
    const int tp = (tf >= 1) ? tf - 1 : 0;
    {
        float r = fminf(fmaxf(s_ratio, 0.0f), 0.92f);
        float cx = r / (1.0f - r);
        const size_t offP = (size_t)tp * NDIM * NDIM;
        const size_t offF = (size_t)fz * NDIM * NDIM;
        for (int idx = tid; idx < NDIM*NDIM; idx += 256) {
            int i = idx >> 6, j = idx & 63;
            float kt = sT[i*PAD + j];
            kt += (kt - g_KT[offP + idx]) * cx;
            sT[i*PAD + j] = kt;
            g_KT[offF + idx] = kt;
            float si = sSa[i*PAD + j];
            si += (si - g_SI[offP + idx]) * cx;
            sSa[i*PAD + j] = si;
            g_SI[offF + idx] = si;
            float pv = sP[i*PAD + j];
            pv += (pv - g_postP[offP + idx]) * cx;
            g_postP[offF + idx] = pv;
        }
        if (tid == 0) {
            g_pref[fz] = g_pref[tf] + (g_pref[tf] - g_pref[tp]) * cx;
            g_tfreeze = tf;
            float r2 = fminf(fmaxf(s_ratio, 0.02f), 0.92f);
            float lnrho = 0.5f * logf(r2);
            int W = (int)(13.0f / (-lnrho)) + 4;
            if (W < 12) W = 12;
            if (W > 120) W = 120;
            g_Wwarm = W;
        }
    }
    __syncthreads();

    // packed frozen matrices (from extrapolated sT / sSa)
    mm64<false,false>(sCW, sH, sF, nullptr, 1.f);   // HF
    __syncthreads();
    mm64<true,false>(sR, sCW, sT, nullptr, 1.f);    // sR[k][j] = sum_m HF[m][k] K[j][m]
    __syncthreads();
    for (int idx = tid; idx < NDIM*NDIM; idx += 256) {
        int k = idx >> 6, j = idx & 63;
        float at = sF[j*PAD + k] - sR[k*PAD + j];
        float kt = sT[k*PAD + j];
        float si = sSa[k*PAD + j];
        int base = (((k >> 1)*64 + j) << 2) + ((k & 1) << 1);
        g_WU[base + 0] = at; g_WU[base + 1] = kt;
        g_K4[base + 0] = kt; g_K4[base + 1] = si;
    }
    if (tid < NDIM) {
        float s = 0.f;
        for (int k = 0; k < NDIM; k++) s += sT[k*PAD + tid] * s_c2s[k];
        g_d0[tid] = db[tid] - s;
    }
}

// =======================================================================
// Phase 2 (fused): segmented mean/likelihood recursion + covariance bcast.
// Grid (NSEG, 16), 256 threads. Frozen data = extrapolated fixed point.
// =======================================================================
__global__ void __launch_bounds__(256, 2)
means_kernel(const float* __restrict__ obs,
             const float* __restrict__ pm0,
             const float* __restrict__ db,
             float* __restrict__ out_means,
             float* __restrict__ out_covs,
             float* __restrict__ out_ll,
             int T, int C)
{
    extern __shared__ float ms[];
    float* sW4 = ms;            // 8192 floats
    float* sK4 = ms + 8192;
    float* sWU = ms + 16384;
    float* sPP = ms + 24576;    // 4096 floats: frozen covariance
    __shared__ __align__(16) float vmbuf[2][4][NDIM];
    __shared__ __align__(16) float vybuf[2][4][NDIM];
    __shared__ __align__(16) float vr[4][NDIM];
    __shared__ float sred[4][2];

    const int tid  = threadIdx.x;
    const int lane = tid >> 6;
    const int j    = tid & 63;
    const int seg  = blockIdx.x;
    const int b    = blockIdx.y * 4 + lane;

    const int t0 = seg * C;
    if (t0 > T) return;
    const int tend = min(t0 + C - 1, T);
    const int tf = g_tfreeze;
    const int fz = (tf + 1 <= MAXT) ? tf + 1 : MAXT;
    const int W = g_Wwarm;

    {
        const float* PPf = g_postP + (size_t)fz * NDIM * NDIM;
        for (int idx = tid; idx < 8192; idx += 256) {
            sW4[idx] = g_W4[idx];
            sK4[idx] = g_K4[idx];
            sWU[idx] = g_WU[idx];
        }
        for (int idx = tid; idx < 4096; idx += 256) sPP[idx] = PPf[idx];
    }
    const float dbj = db[j], c2j = g_c2[j], o0j = g_o0[j];
    const float pm0j = pm0[j], d0j = g_d0[j];
    const float pref_f = g_pref[fz];

    int ts = t0 - W;
    const bool frozen_warm = (t0 > 0) && (ts > tf);

    int p = 0;
    vmbuf[0][lane][j] = 0.f;
    vmbuf[1][lane][j] = 0.f;
    if (frozen_warm) vybuf[0][lane][j] = obs[((size_t)ts * NB + b) * NDIM + j];
    __syncthreads();

    if (frozen_warm) {
        for (int t = ts; t < t0; t++) {
            vybuf[p^1][lane][j] = obs[((size_t)(t+1) * NB + b) * NDIM + j];
            const float* vml = vmbuf[p][lane];
            const float* vyl = vybuf[p][lane];
            float m0 = 0.f, m1 = 0.f;
#pragma unroll
            for (int k = 0; k < NDIM; k += 4) {
                float4 v  = *(const float4*)&vml[k];
                float4 yv = *(const float4*)&vyl[k];
                float4 w0 = *(const float4*)&sWU[((k>>1)*64 + j) << 2];
                float4 w1 = *(const float4*)&sWU[(((k>>1)+1)*64 + j) << 2];
                m0 += v.x*w0.x + yv.x*w0.y;
                m1 += v.y*w0.z + yv.y*w0.w;
                m0 += v.z*w1.x + yv.z*w1.y;
                m1 += v.w*w1.z + yv.w*w1.w;
            }
            vmbuf[p^1][lane][j] = m0 + m1 + d0j;
            p ^= 1;
            __syncthreads();
        }
    }

    const int tstart = frozen_warm ? t0 : 0;
    for (int t = tstart; t <= tend; t++) {
        const float y = obs[((size_t)t * NB + b) * NDIM + j];
        const float* vml = vmbuf[p][lane];
        float pm, o;
        if (t == 0) {
            pm = pm0j; o = o0j;
        } else {
            float a0 = 0.f, a1 = 0.f, c0 = 0.f, c1 = 0.f;
#pragma unroll
            for (int k = 0; k < NDIM; k += 4) {
                float4 v  = *(const float4*)&vml[k];
                float4 w0 = *(const float4*)&sW4[((k>>1)*64 + j) << 2];
                float4 w1 = *(const float4*)&sW4[(((k>>1)+1)*64 + j) << 2];
                a0 += v.x*w0.x; c0 += v.x*w0.y;
                a1 += v.y*w0.z; c1 += v.y*w0.w;
                a0 += v.z*w1.x; c0 += v.z*w1.y;
                a1 += v.w*w1.z; c1 += v.w*w1.w;
            }
            pm = a0 + a1 + dbj;
            o  = c0 + c1 + c2j;
        }
        const float r = y - o;
        vr[lane][j] = r;
        __syncthreads();

        const float* vrl = vr[lane];
        float mu0 = 0.f, mu1 = 0.f, u0 = 0.f, u1 = 0.f;
        if (t > tf) {
#pragma unroll
            for (int k = 0; k < NDIM; k += 4) {
                float4 r4 = *(const float4*)&vrl[k];
                float4 w0 = *(const float4*)&sK4[((k>>1)*64 + j) << 2];
                float4 w1 = *(const float4*)&sK4[(((k>>1)+1)*64 + j) << 2];
                mu0 += r4.x*w0.x; u0 += r4.x*w0.y;
                mu1 += r4.y*w0.z; u1 += r4.y*w0.w;
                mu0 += r4.z*w1.x; u0 += r4.z*w1.y;
                mu1 += r4.w*w1.z; u1 += r4.w*w1.w;
            }
        } else {
            const float* KTp = g_KT + (size_t)t * NDIM * NDIM;
            const float* SIp = g_SI + (size_t)t * NDIM * NDIM;
#pragma unroll 4
            for (int k = 0; k < NDIM; k += 2) {
                float r0 = vrl[k], r1 = vrl[k+1];
                mu0 += r0 * KTp[k*NDIM + j];     u0 += r0 * SIp[k*NDIM + j];
                mu1 += r1 * KTp[(k+1)*NDIM + j]; u1 += r1 * SIp[(k+1)*NDIM + j];
            }
        }
        const float mnew = pm + mu0 + mu1;
        vmbuf[p^1][lane][j] = mnew;

        if (t >= t0) {
            out_means[((size_t)t * NB + b) * NDIM + j] = mnew;
            float q = r * (u0 + u1);
#pragma unroll
            for (int o2 = 16; o2 > 0; o2 >>= 1)
                q += __shfl_down_sync(0xffffffffu, q, o2);
            if ((j & 31) == 0) sred[lane][j >> 5] = q;

            float4* dst = (float4*)(out_covs + ((size_t)t * NB + b) * NDIM * NDIM);
            const float4* s4 = (t > tf) ? (const float4*)sPP
                                        : (const float4*)(g_postP + (size_t)t * NDIM * NDIM);
#pragma unroll
            for (int e = 0; e < 16; e++) dst[j + e*64] = s4[j + e*64];
        }
        __syncthreads();
        if (j == 0 && t >= t0) {
            float pref = (t > tf) ? pref_f : g_pref[t];
            out_ll[(size_t)t * NB + b] = pref - 0.5f * (sred[lane][0] + sred[lane][1]);
        }
        p ^= 1;
    }
}

// =======================================================================
extern "C" void kernel_launch(void* const* d_in, const int* in_sizes, int n_in,
                              void* d_out, int out_size)
{
    int base = n_in - 9;
    if (base < 0) base = 0;

    const float* obs = (const float*)d_in[base + 0];
    const float* pm0 = (const float*)d_in[base + 1];
    const float* pc  = (const float*)d_in[base + 2];
    const float* Fw  = (const float*)d_in[base + 3];
    const float* db  = (const float*)d_in[base + 4];
    const float* dc  = (const float*)d_in[base + 5];
    const float* Hw  = (const float*)d_in[base + 6];
    const float* ob  = (const float*)d_in[base + 7];
    const float* oc  = (const float*)d_in[base + 8];

    int T = in_sizes[base + 0] / (NB * NDIM) - 1;
    if (T > MAXT) T = MAXT;
    if (T < 1) T = 1;

    float* out_means = (float*)d_out;
    float* out_covs  = out_means + (size_t)(T + 1) * NB * NDIM;
    float* out_ll    = out_covs  + (size_t)(T + 1) * NB * NDIM * NDIM;

    const int C = (T + 1 + NSEG - 1) / NSEG;

    cudaFuncSetAttribute(riccati_kernel,
                         cudaFuncAttributeMaxDynamicSharedMemorySize, R_SMEM);
    cudaFuncSetAttribute(means_kernel,
                         cudaFuncAttributeMaxDynamicSharedMemorySize, M_SMEM);

    riccati_kernel<<<1, 256, R_SMEM>>>(pc, Fw, dc, Hw, oc, pm0, db, ob, T);
    dim3 mg(NSEG, NB / 4);
    means_kernel<<<mg, 256, M_SMEM>>>(obs, pm0, db, out_means, out_covs, out_ll, T, C);
}

// round 8
// speedup vs baseline: 1.1825x; 1.1825x over previous
#include <cuda_runtime.h>
#include <math.h>
#include <stdint.h>

#define NDIM 64
#define NB 64
#define MAXT 512
#define PAD 65
#define NMAT (NDIM*PAD)
#define HL2PI 0.91893853320467274178f
#define R_SMEM (9*NMAT*4)
#define M_SMEM ((2*8192 + 4096)*4)
#define NSEG 18

// ---------------- static device scratch ----------------
__device__ float g_KT[(MAXT+1)*NDIM*NDIM];
__device__ float g_SI[(MAXT+1)*NDIM*NDIM];
__device__ float g_postP[(MAXT+1)*NDIM*NDIM];
__device__ float g_pref[MAXT+1];
__device__ float g_W4[2*NDIM*NDIM];   // packed {F^T,(HF)^T} per k-pair
__device__ float g_K4[2*NDIM*NDIM];   // packed {K^T_inf, SI_inf}
__device__ float g_WU[2*NDIM*NDIM];   // packed {A^T, K^T_inf}
__device__ float g_c2[NDIM];
__device__ float g_o0[NDIM];
__device__ float g_d0[NDIM];
__device__ int   g_tfreeze;
__device__ int   g_Wwarm;

// ---------------- 64x64 matmul on PAD-strided smem, 256 threads ----------------
template<bool TA, bool TB>
__device__ __forceinline__ void mm64(float* C, const float* A, const float* B,
                                     const float* Cadd, float sgn)
{
    const int tid = threadIdx.x;
    const int i0 = (tid >> 4) << 2;
    const int j0 = (tid & 15) << 2;
    float acc[4][4];
#pragma unroll
    for (int r = 0; r < 4; r++)
#pragma unroll
        for (int c = 0; c < 4; c++) acc[r][c] = 0.f;
#pragma unroll 4
    for (int k = 0; k < NDIM; k++) {
        float a[4], b[4];
#pragma unroll
        for (int r = 0; r < 4; r++) a[r] = TA ? A[k*PAD + (i0+r)] : A[(i0+r)*PAD + k];
#pragma unroll
        for (int c = 0; c < 4; c++) b[c] = TB ? B[(j0+c)*PAD + k] : B[k*PAD + (j0+c)];
#pragma unroll
        for (int r = 0; r < 4; r++)
#pragma unroll
            for (int c = 0; c < 4; c++) acc[r][c] += a[r] * b[c];
    }
#pragma unroll
    for (int r = 0; r < 4; r++)
#pragma unroll
        for (int c = 0; c < 4; c++) {
            float base = Cadd ? Cadd[(i0+r)*PAD + (j0+c)] : 0.f;
            C[(i0+r)*PAD + (j0+c)] = base + sgn * acc[r][c];
        }
}

// symmetric-output matmul, 136 blocks striped across all 8 warps (SMSP-balanced)
template<bool TA, bool TB>
__device__ __forceinline__ void mm64_sym(float* C, const float* A, const float* B,
                                         const float* Cadd, float sgn,
                                         int i0, int j0, bool act)
{
    if (!act) return;
    float acc[4][4];
#pragma unroll
    for (int r = 0; r < 4; r++)
#pragma unroll
        for (int c = 0; c < 4; c++) acc[r][c] = 0.f;
#pragma unroll 4
    for (int k = 0; k < NDIM; k++) {
        float a[4], b[4];
#pragma unroll
        for (int r = 0; r < 4; r++) a[r] = TA ? A[k*PAD + (i0+r)] : A[(i0+r)*PAD + k];
#pragma unroll
        for (int c = 0; c < 4; c++) b[c] = TB ? B[(j0+c)*PAD + k] : B[k*PAD + (j0+c)];
#pragma unroll
        for (int r = 0; r < 4; r++)
#pragma unroll
            for (int c = 0; c < 4; c++) acc[r][c] += a[r] * b[c];
    }
#pragma unroll
    for (int r = 0; r < 4; r++)
#pragma unroll
        for (int c = 0; c < 4; c++) {
            float base = Cadd ? Cadd[(i0+r)*PAD + (j0+c)] : 0.f;
            float v = base + sgn * acc[r][c];
            C[(i0+r)*PAD + (j0+c)] = v;
            if (i0 != j0) C[(j0+c)*PAD + (i0+r)] = v;
        }
}

__device__ __forceinline__ void ld_mat(float* dst, const float* __restrict__ src) {
    for (int idx = threadIdx.x; idx < NDIM*NDIM; idx += blockDim.x)
        dst[(idx >> 6)*PAD + (idx & 63)] = src[idx];
}

// =======================================================================
// Phase 1: Riccati recursion, one CTA, 256 threads.
// =======================================================================
__global__ void riccati_kernel(const float* __restrict__ prior_chol,
                               const float* __restrict__ Fw,
                               const float* __restrict__ dyn_chol,
                               const float* __restrict__ Hw,
                               const float* __restrict__ obs_chol,
                               const float* __restrict__ pm0,
                               const float* __restrict__ db,
                               const float* __restrict__ ob,
                               int T)
{
    extern __shared__ float sm[];
    float* sP    = sm + 0*NMAT;
    float* sT    = sm + 1*NMAT;
    float* sCW   = sm + 2*NMAT;
    float* sSa   = sm + 3*NMAT;
    float* sF    = sm + 4*NMAT;
    float* sH    = sm + 5*NMAT;
    float* sQ    = sm + 6*NMAT;
    float* sR    = sm + 7*NMAT;
    float* sPrev = sm + 8*NMAT;
    __shared__ float s_red8[8];
    __shared__ float s_row[2][NDIM];
    __shared__ float s_col[2][NDIM];
    __shared__ float s_c2s[NDIM];
    __shared__ int   s_conv;
    __shared__ float s_ratio;

    const int tid = threadIdx.x;
    const int gi0 = (tid >> 4) << 2;
    const int gj0 = (tid & 15) << 2;

    // SMSP-balanced upper block-triangle mapping: block m -> warp (m&7), lane (m>>3)
    int sbi = 0, sbj = 0;
    bool s_act = false;
    {
        const int warp = tid >> 5, wl = tid & 31;
        int m = wl * 8 + warp;
        if (wl < 17 && m < 136) {
            s_act = true;
            int mm = m, r = 0;
            while (mm >= 16 - r) { mm -= 16 - r; r++; }
            sbi = r; sbj = r + mm;
        }
    }
    const int si0 = sbi << 2, sj0 = sbj << 2;

    ld_mat(sF, Fw); ld_mat(sH, Hw); ld_mat(sT, dyn_chol);
    __syncthreads();
    mm64_sym<false,true>(sQ, sT, sT, nullptr, 1.f, si0, sj0, s_act);
    __syncthreads();
    ld_mat(sT, obs_chol);
    __syncthreads();
    mm64_sym<false,true>(sR, sT, sT, nullptr, 1.f, si0, sj0, s_act);
    __syncthreads();
    ld_mat(sT, prior_chol);
    __syncthreads();
    mm64_sym<false,true>(sP, sT, sT, nullptr, 1.f, si0, sj0, s_act);
    __syncthreads();

    mm64<false,false>(sT, sH, sF, nullptr, 1.f);   // HF
    __syncthreads();
    for (int idx = tid; idx < NDIM*NDIM; idx += 256) {
        int k = idx >> 6, j = idx & 63;
        int base = (((k >> 1)*64 + j) << 2) + ((k & 1) << 1);
        g_W4[base + 0] = sF[j*PAD + k];
        g_W4[base + 1] = sT[j*PAD + k];
    }
    if (tid < NDIM) {
        float c = 0.f, o0 = 0.f;
        for (int k = 0; k < NDIM; k++) {
            float h = sH[tid*PAD + k];
            c  += h * db[k];
            o0 += h * pm0[k];
        }
        s_c2s[tid] = c + ob[tid];
        g_c2[tid] = c + ob[tid];
        g_o0[tid] = o0 + ob[tid];
    }
    __syncthreads();

    int tf = T;
    float rprev = 1e30f;
    for (int t = 0; t <= T; t++) {
        if (t > 0) {
            mm64<false,false>(sT, sF, sP, nullptr, 1.f);
            __syncthreads();
            mm64_sym<false,true>(sP, sT, sF, sQ, 1.f, si0, sj0, s_act);
            __syncthreads();
        }
        mm64<false,true>(sCW, sP, sH, nullptr, 1.f);
        __syncthreads();
        mm64_sym<false,false>(sSa, sH, sCW, sR, 1.f, si0, sj0, s_act);
        __syncthreads();

        // register-resident Gauss-Jordan inversion of S
        {
            float a[4][4];
#pragma unroll
            for (int r = 0; r < 4; r++)
#pragma unroll
                for (int c = 0; c < 4; c++) a[r][c] = sSa[(gi0+r)*PAD + gj0 + c];

            float logsum = 0.f;
            for (int p = 0; p < NDIM; p++) {
                const int buf = p & 1;
                if ((p >> 2) == (tid >> 4)) {
                    const int pr = p - gi0;
#pragma unroll
                    for (int c = 0; c < 4; c++) s_row[buf][gj0 + c] = a[pr][c];
                }
                if ((p >> 2) == (tid & 15)) {
                    const int pc = p - gj0;
#pragma unroll
                    for (int r = 0; r < 4; r++) s_col[buf][gi0 + r] = a[r][pc];
                }
                __syncthreads();
                const float piv = s_row[buf][p];
                const float d = 1.0f / piv;
                if (tid == 0) logsum += logf(piv);
                float4 rowv = *(const float4*)&s_row[buf][gj0];
                float4 colv = *(const float4*)&s_col[buf][gi0];
                const float* rv = (const float*)&rowv;
                const float* cv = (const float*)&colv;
#pragma unroll
                for (int r = 0; r < 4; r++) {
                    const float aip = cv[r];
                    const bool ip = (gi0 + r == p);
#pragma unroll
                    for (int c = 0; c < 4; c++) {
                        const float apj = rv[c];
                        const bool jp = (gj0 + c == p);
                        float v = a[r][c] - aip * apj * d;
                        if (ip) v = apj * d;
                        if (jp) v = -aip * d;
                        if (ip && jp) v = d;
                        a[r][c] = v;
                    }
                }
            }
            if (tid == 0) g_pref[t] = -NDIM * HL2PI - 0.5f * logsum;
#pragma unroll
            for (int r = 0; r < 4; r++)
#pragma unroll
                for (int c = 0; c < 4; c++) sSa[(gi0+r)*PAD + gj0 + c] = a[r][c];
        }
        __syncthreads();

        mm64<true,true>(sT, sSa, sCW, nullptr, 1.f);
        __syncthreads();
        mm64_sym<true,true>(sP, sT, sCW, sP, -1.f, si0, sj0, s_act);
        __syncthreads();

        float mymax = 0.f;
        const size_t off = (size_t)t * NDIM * NDIM;
        for (int idx = tid; idx < NDIM*NDIM; idx += 256) {
            int i = idx >> 6, j = idx & 63;
            float v = sP[i*PAD + j];
            mymax = fmaxf(mymax, fabsf(v - sPrev[i*PAD + j]));
            sPrev[i*PAD + j] = v;
            g_postP[off + idx] = v;
            g_KT[off + idx]    = sT[i*PAD + j];
            g_SI[off + idx]    = sSa[i*PAD + j];
        }
#pragma unroll
        for (int o = 16; o > 0; o >>= 1)
            mymax = fmaxf(mymax, __shfl_xor_sync(0xffffffffu, mymax, o));
        if ((tid & 31) == 0) s_red8[tid >> 5] = mymax;
        __syncthreads();
        if (tid == 0) {
            float mx = s_red8[0];
#pragma unroll
            for (int i = 1; i < 8; i++) mx = fmaxf(mx, s_red8[i]);
            s_ratio = mx / fmaxf(rprev, 1e-30f);
            rprev = mx;
            s_conv = (t >= 1 && mx < 3e-5f) ? 1 : 0;
        }
        __syncthreads();
        if (s_conv) { tf = t; break; }
    }

    // epilogue: Aitken extrapolation to fixed point in slot fz = tf+1
    const int fz = (tf + 1 <= MAXT) ? tf + 1 : MAXT;
    const int tp = (tf >= 1) ? tf - 1 : 0;
    {
        float r = fminf(fmaxf(s_ratio, 0.0f), 0.92f);
        float cx = r / (1.0f - r);
        const size_t offP = (size_t)tp * NDIM * NDIM;
        const size_t offF = (size_t)fz * NDIM * NDIM;
        for (int idx = tid; idx < NDIM*NDIM; idx += 256) {
            int i = idx >> 6, j = idx & 63;
            float kt = sT[i*PAD + j];
            kt += (kt - g_KT[offP + idx]) * cx;
            sT[i*PAD + j] = kt;
            g_KT[offF + idx] = kt;
            float si = sSa[i*PAD + j];
            si += (si - g_SI[offP + idx]) * cx;
            sSa[i*PAD + j] = si;
            g_SI[offF + idx] = si;
            float pv = sP[i*PAD + j];
            pv += (pv - g_postP[offP + idx]) * cx;
            g_postP[offF + idx] = pv;
        }
        if (tid == 0) {
            g_pref[fz] = g_pref[tf] + (g_pref[tf] - g_pref[tp]) * cx;
            g_tfreeze = tf;
            float r2 = fminf(fmaxf(s_ratio, 0.02f), 0.92f);
            float lnrho = 0.5f * logf(r2);
            int W = (int)(13.0f / (-lnrho)) + 4;
            if (W < 12) W = 12;
            if (W > 120) W = 120;
            g_Wwarm = W;
        }
    }
    __syncthreads();

    mm64<false,false>(sCW, sH, sF, nullptr, 1.f);   // HF
    __syncthreads();
    mm64<true,false>(sR, sCW, sT, nullptr, 1.f);    // sR[k][j] = sum_m HF[m][k] K[j][m]
    __syncthreads();
    for (int idx = tid; idx < NDIM*NDIM; idx += 256) {
        int k = idx >> 6, j = idx & 63;
        float at = sF[j*PAD + k] - sR[k*PAD + j];   // A^T, A = F - K*HF
        float kt = sT[k*PAD + j];
        float si = sSa[k*PAD + j];
        int base = (((k >> 1)*64 + j) << 2) + ((k & 1) << 1);
        g_WU[base + 0] = at; g_WU[base + 1] = kt;
        g_K4[base + 0] = kt; g_K4[base + 1] = si;
    }
    if (tid < NDIM) {
        float s = 0.f;
        for (int k = 0; k < NDIM; k++) s += sT[k*PAD + tid] * s_c2s[k];
        g_d0[tid] = db[tid] - s;
    }
}

// =======================================================================
// Phase 2: segmented means/likelihood + covariance output (TMA bulk).
// Grid (NSEG, 16), 256 threads = (k-slice s | batch lane) x 64 j.
// =======================================================================
__global__ void __launch_bounds__(256, 2)
means_kernel(const float* __restrict__ obs,
             const float* __restrict__ pm0,
             const float* __restrict__ db,
             float* __restrict__ out_means,
             float* __restrict__ out_covs,
             float* __restrict__ out_ll,
             int T, int C)
{
    extern __shared__ float ms[];
    float* sW4 = ms;            // 8192: {F^T,HF^T}
    float* sKW = ms + 8192;     // 8192: warm {A^T,KT} then frozen {KT,SI}
    float* sPP = ms + 16384;    // 4096: frozen covariance
    __shared__ __align__(16) float vmbuf[2][4][NDIM];
    __shared__ __align__(16) float vybuf[2][4][NDIM];
    __shared__ __align__(16) float vr[4][NDIM];
    __shared__ __align__(16) float sRed[2048];
    __shared__ float sred[4][2];

    const int tid  = threadIdx.x;
    const int s    = tid >> 6;      // k-slice role in passes, batch lane otherwise
    const int j    = tid & 63;
    const int lane = s;
    const int seg  = blockIdx.x;
    const int bbase = blockIdx.y * 4;
    const int b    = bbase + lane;

    const int t0 = seg * C;
    if (t0 > T) return;
    const int tend = min(t0 + C - 1, T);
    const int tf = g_tfreeze;
    const int fz = (tf + 1 <= MAXT) ? tf + 1 : MAXT;
    const int W = g_Wwarm;

    int ts = t0 - W;
    const bool fwarm = (t0 > 0) && (ts > tf);
    int tstart = ts < 0 ? 0 : ts;

    {
        const float* kw = fwarm ? g_WU : g_K4;
        const float* PPf = g_postP + (size_t)fz * 4096;
        for (int idx = tid; idx < 8192; idx += 256) {
            sW4[idx] = g_W4[idx];
            sKW[idx] = kw[idx];
        }
        for (int idx = tid; idx < 4096; idx += 256) sPP[idx] = PPf[idx];
    }
    const float dbj = db[j], c2j = g_c2[j], o0j = g_o0[j];
    const float pm0j = pm0[j], d0j = g_d0[j];
    const float pref_f = g_pref[fz];

    uint32_t sppa;
    asm("{ .reg .u64 ta; cvta.to.shared.u64 ta, %1; cvt.u32.u64 %0, ta; }"
        : "=r"(sppa) : "l"(sPP));

    vmbuf[0][lane][j] = 0.f;
    vmbuf[1][lane][j] = 0.f;
    vybuf[0][lane][j] = obs[((size_t)tstart * NB + b) * NDIM + j];
    __syncthreads();
    if (tid == 0) asm volatile("fence.proxy.async.shared::cta;" ::: "memory");

    int p = 0;
    if (fwarm) {
        for (int t = tstart; t < t0; t++) {
            const float ynext = obs[((size_t)(t+1) * NB + b) * NDIM + j];
            float m[4] = {0.f, 0.f, 0.f, 0.f};
            const int k0 = s << 4;
#pragma unroll
            for (int kk = 0; kk < 16; kk += 2) {
                const int k = k0 + kk;
                float4 w = *(const float4*)&sKW[((k >> 1)*64 + j) << 2];
#pragma unroll
                for (int b4 = 0; b4 < 4; b4++) {
                    float2 v  = *(const float2*)&vmbuf[p][b4][k];
                    float2 yv = *(const float2*)&vybuf[p][b4][k];
                    m[b4] += v.x*w.x + yv.x*w.y + v.y*w.z + yv.y*w.w;
                }
            }
#pragma unroll
            for (int b4 = 0; b4 < 4; b4++)
                sRed[((s*4 + b4) << 6) | j] = m[b4];
            __syncthreads();
            float mm = d0j;
#pragma unroll
            for (int s2 = 0; s2 < 4; s2++) mm += sRed[((s2*4 + lane) << 6) | j];
            vmbuf[p^1][lane][j] = mm;
            vybuf[p^1][lane][j] = ynext;
            p ^= 1;
            __syncthreads();
        }
        // swap sKW to frozen {KT, SI}
        for (int idx = tid; idx < 8192; idx += 256) sKW[idx] = g_K4[idx];
        __syncthreads();
    }

    for (int t = (fwarm ? t0 : tstart); t <= tend; t++) {
        const bool frozen = (t > tf);
        const bool emit = (t >= t0);

        // async covariance store (constant frozen tile in smem)
        if (frozen && emit && tid == 0) {
#pragma unroll
            for (int b4 = 0; b4 < 4; b4++) {
                float* g = out_covs + ((size_t)t * NB + bbase + b4) * 4096;
                asm volatile("cp.async.bulk.global.shared::cta.bulk_group [%0], [%1], %2;"
                             :: "l"(g), "r"(sppa), "r"(16384) : "memory");
            }
            asm volatile("cp.async.bulk.commit_group;" ::: "memory");
            asm volatile("cp.async.bulk.wait_group.read 6;" ::: "memory");
        }

        float ynext = 0.f;
        if (t < tend) ynext = obs[((size_t)(t+1) * NB + b) * NDIM + j];

        // ---- pass A: mean/obs propagation (thread = (k-slice, j)) ----
        {
            float a[4] = {0.f,0.f,0.f,0.f}, c[4] = {0.f,0.f,0.f,0.f};
            const int k0 = s << 4;
#pragma unroll
            for (int kk = 0; kk < 16; kk += 2) {
                const int k = k0 + kk;
                float4 w = *(const float4*)&sW4[((k >> 1)*64 + j) << 2];
#pragma unroll
                for (int b4 = 0; b4 < 4; b4++) {
                    float2 v = *(const float2*)&vmbuf[p][b4][k];
                    a[b4] += v.x*w.x + v.y*w.z;
                    c[b4] += v.x*w.y + v.y*w.w;
                }
            }
#pragma unroll
            for (int b4 = 0; b4 < 4; b4++)
                *(float2*)&sRed[((((s*4 + b4) << 6) | j) << 1)] = make_float2(a[b4], c[b4]);
        }
        __syncthreads();

        // ---- (lane, j): residual ----
        float pm, o;
        {
            float sa_ = 0.f, sc_ = 0.f;
#pragma unroll
            for (int s2 = 0; s2 < 4; s2++) {
                float2 f = *(const float2*)&sRed[((((s2*4 + lane) << 6) | j) << 1)];
                sa_ += f.x; sc_ += f.y;
            }
            pm = sa_ + dbj; o = sc_ + c2j;
        }
        if (t == 0) { pm = pm0j; o = o0j; }
        const float y = vybuf[p][lane][j];
        const float r = y - o;
        vr[lane][j] = r;
        __syncthreads();

        // ---- pass B: gain + whitening ----
        float mu, u;
        if (frozen) {
            float m2[4] = {0.f,0.f,0.f,0.f}, u2[4] = {0.f,0.f,0.f,0.f};
            const int k0 = s << 4;
#pragma unroll
            for (int kk = 0; kk < 16; kk += 2) {
                const int k = k0 + kk;
                float4 w = *(const float4*)&sKW[((k >> 1)*64 + j) << 2];
#pragma unroll
                for (int b4 = 0; b4 < 4; b4++) {
                    float2 v = *(const float2*)&vr[b4][k];
                    m2[b4] += v.x*w.x + v.y*w.z;
                    u2[b4] += v.x*w.y + v.y*w.w;
                }
            }
#pragma unroll
            for (int b4 = 0; b4 < 4; b4++)
                *(float2*)&sRed[((((s*4 + b4) << 6) | j) << 1)] = make_float2(m2[b4], u2[b4]);
            __syncthreads();
            float sm_ = 0.f, su_ = 0.f;
#pragma unroll
            for (int s2 = 0; s2 < 4; s2++) {
                float2 f = *(const float2*)&sRed[((((s2*4 + lane) << 6) | j) << 1)];
                sm_ += f.x; su_ += f.y;
            }
            mu = sm_; u = su_;
        } else {
            const float* KTp = g_KT + (size_t)t * 4096;
            const float* SIp = g_SI + (size_t)t * 4096;
            float mu0 = 0.f, mu1 = 0.f, u0 = 0.f, u1 = 0.f;
#pragma unroll 4
            for (int k = 0; k < NDIM; k += 2) {
                float r0 = vr[lane][k], r1 = vr[lane][k+1];
                mu0 += r0 * KTp[k*64 + j];     u0 += r0 * SIp[k*64 + j];
                mu1 += r1 * KTp[(k+1)*64 + j]; u1 += r1 * SIp[(k+1)*64 + j];
            }
            mu = mu0 + mu1; u = u0 + u1;
        }

        const float mnew = pm + mu;
        vmbuf[p^1][lane][j] = mnew;
        vybuf[p^1][lane][j] = ynext;

        if (emit) {
            out_means[((size_t)t * NB + b) * NDIM + j] = mnew;
            float q = r * u;
#pragma unroll
            for (int o2 = 16; o2 > 0; o2 >>= 1)
                q += __shfl_down_sync(0xffffffffu, q, o2);
            if ((j & 31) == 0) sred[lane][j >> 5] = q;
            if (!frozen) {
                float4* dst = (float4*)(out_covs + ((size_t)t * NB + b) * 4096);
                const float4* s4 = (const float4*)(g_postP + (size_t)t * 4096);
#pragma unroll
                for (int e = 0; e < 16; e++) dst[j + e*64] = s4[j + e*64];
            }
        }
        __syncthreads();
        if (emit && j == 0) {
            float pref = frozen ? pref_f : g_pref[t];
            out_ll[(size_t)t * NB + b] = pref - 0.5f * (sred[lane][0] + sred[lane][1]);
        }
        p ^= 1;
    }
    if (tid == 0) asm volatile("cp.async.bulk.wait_group 0;" ::: "memory");
}

// =======================================================================
extern "C" void kernel_launch(void* const* d_in, const int* in_sizes, int n_in,
                              void* d_out, int out_size)
{
    int base = n_in - 9;
    if (base < 0) base = 0;

    const float* obs = (const float*)d_in[base + 0];
    const float* pm0 = (const float*)d_in[base + 1];
    const float* pc  = (const float*)d_in[base + 2];
    const float* Fw  = (const float*)d_in[base + 3];
    const float* db  = (const float*)d_in[base + 4];
    const float* dc  = (const float*)d_in[base + 5];
    const float* Hw  = (const float*)d_in[base + 6];
    const float* ob  = (const float*)d_in[base + 7];
    const float* oc  = (const float*)d_in[base + 8];

    int T = in_sizes[base + 0] / (NB * NDIM) - 1;
    if (T > MAXT) T = MAXT;
    if (T < 1) T = 1;

    float* out_means = (float*)d_out;
    float* out_covs  = out_means + (size_t)(T + 1) * NB * NDIM;
    float* out_ll    = out_covs  + (size_t)(T + 1) * NB * NDIM * NDIM;

    const int C = (T + 1 + NSEG - 1) / NSEG;

    cudaFuncSetAttribute(riccati_kernel,
                         cudaFuncAttributeMaxDynamicSharedMemorySize, R_SMEM);
    cudaFuncSetAttribute(means_kernel,
                         cudaFuncAttributeMaxDynamicSharedMemorySize, M_SMEM);

    riccati_kernel<<<1, 256, R_SMEM>>>(pc, Fw, dc, Hw, oc, pm0, db, ob, T);
    dim3 mg(NSEG, NB / 4);
    means_kernel<<<mg, 256, M_SMEM>>>(obs, pm0, db, out_means, out_covs, out_ll, T, C);
}